// round 4
// baseline (speedup 1.0000x reference)
#include <cuda_runtime.h>
#include <cstdint>
#include <cstddef>

// ---------------- Problem constants ----------------
// spk: [65536, 1024] fp32 (A, K-major), W: [1024, 1024] fp32 (B rows = out dim, K-major),
// b: [1024], beta: [1024].
// out: out_seq [65536 x 1024] then final_mem [65536] at float offset 67108864.
#define M_TOTAL 65536
#define N_TOTAL 1024
#define K_TOTAL 1024

#define BM 128
#define BN 256
#define BK 32                      // 32 floats = 128 B per smem row
#define KC (K_TOTAL / BK)          // 32 chunks
#define NSTG 3
#define A_BYTES (BM * 128)         // 16 KB
#define B_BYTES (BN * 128)         // 32 KB
#define STG_BYTES (A_BYTES + B_BYTES)   // 48 KB
#define SMEM_DYN (1024 + NSTG * STG_BYTES)

// ---------------- PTX helpers (baseline features only: sm_80-class) ----------------
__device__ __forceinline__ uint32_t smem_u32(const void* p) {
    uint32_t r;
    asm("{ .reg .u64 t; cvta.to.shared.u64 t, %1; cvt.u32.u64 %0, t; }" : "=r"(r) : "l"(p));
    return r;
}
__device__ __forceinline__ void cp16(uint32_t dst, const void* src) {
    asm volatile("cp.async.cg.shared.global [%0], [%1], 16;"
                 :: "r"(dst), "l"(__cvta_generic_to_global(src)) : "memory");
}
#define CP_COMMIT() asm volatile("cp.async.commit_group;" ::: "memory")
template <int N>
__device__ __forceinline__ void cp_wait() {
    asm volatile("cp.async.wait_group %0;" :: "n"(N) : "memory");
}
__device__ __forceinline__ void ldmatrix_x4(uint32_t* r, uint32_t addr) {
    asm volatile("ldmatrix.sync.aligned.m8n8.x4.shared.b16 {%0,%1,%2,%3}, [%4];"
                 : "=r"(r[0]), "=r"(r[1]), "=r"(r[2]), "=r"(r[3]) : "r"(addr));
}
__device__ __forceinline__ uint32_t f2tf32(uint32_t bits) {
    uint32_t o;
    asm("cvt.rna.tf32.f32 %0, %1;" : "=r"(o) : "f"(__uint_as_float(bits)));
    return o;
}
__device__ __forceinline__ void mma_tf32(float* d, const uint32_t* a,
                                         uint32_t b0, uint32_t b1) {
    asm volatile(
        "mma.sync.aligned.m16n8k8.row.col.f32.tf32.tf32.f32 "
        "{%0,%1,%2,%3}, {%4,%5,%6,%7}, {%8,%9}, {%0,%1,%2,%3};"
        : "+f"(d[0]), "+f"(d[1]), "+f"(d[2]), "+f"(d[3])
        : "r"(a[0]), "r"(a[1]), "r"(a[2]), "r"(a[3]), "r"(b0), "r"(b1));
}

// ---------------- producer: gmem -> swizzled smem ----------------
// A tile: 128 rows x 32 floats; B tile: 256 rows x 32 floats. Row = 128B, SW128 swizzle:
// 16B-granule g stored at g ^ (row & 7).
__device__ __forceinline__ void load_chunk(int tid, uint32_t stage_base, int kc,
                                           const float* __restrict__ A,
                                           const float* __restrict__ W,
                                           int m_base, int n_base) {
    const float* gA = A + (size_t)m_base * K_TOTAL + kc * BK;
    const float* gB = W + (size_t)n_base * K_TOTAL + kc * BK;
    uint32_t sA = stage_base;
    uint32_t sB = stage_base + A_BYTES;
#pragma unroll
    for (int i = 0; i < 4; ++i) {                    // A: 1024 granules / 256 thr
        int idx = tid + i * 256;
        int row = idx >> 3, g = idx & 7;
        uint32_t sw = row * 128 + ((g ^ (row & 7)) << 4);
        cp16(sA + sw, gA + (size_t)row * K_TOTAL + g * 4);
    }
#pragma unroll
    for (int i = 0; i < 8; ++i) {                    // B: 2048 granules / 256 thr
        int idx = tid + i * 256;
        int row = idx >> 3, g = idx & 7;
        uint32_t sw = row * 128 + ((g ^ (row & 7)) << 4);
        cp16(sB + sw, gB + (size_t)row * K_TOTAL + g * 4);
    }
}

// ---------------- GEMM: cur = spk @ W^T + b -> out_seq region ----------------
__global__ void __launch_bounds__(256, 1)
gemm_tf32_kernel(const float* __restrict__ A, const float* __restrict__ W,
                 const float* __restrict__ bias, float* __restrict__ out) {
    extern __shared__ char smem[];
    const int tid = threadIdx.x;
    const int lane = tid & 31;
    const int wid = tid >> 5;
    const int warp_m = wid & 1;        // 2 warp-rows  (64 M each)
    const int warp_n = wid >> 1;       // 4 warp-cols  (64 N each)
    const int n_base = blockIdx.x * BN;
    const int m_base = blockIdx.y * BM;

    uint32_t AL = (smem_u32(smem) + 1023) & ~1023u;

    // ldmatrix row constants (same formula for A m-tiles and B n-pairs):
    // row(t) = warp_dim*64 + t*16 + ((lane>>3)&1)*8 + (lane&7)
    const int lrow = ((lane >> 3) & 1) * 8 + (lane & 7);
    const int ghi = lane >> 4;         // granule high bit from matrix index 2/3
    uint32_t aOff[4], aSw[4], bOff[4], bSw[4];
#pragma unroll
    for (int t = 0; t < 4; ++t) {
        int ra = warp_m * 64 + t * 16 + lrow;
        int rb = warp_n * 64 + t * 16 + lrow;
        aOff[t] = ra * 128; aSw[t] = ra & 7;
        bOff[t] = rb * 128; bSw[t] = rb & 7;
    }

    float acc[4][8][4];
#pragma unroll
    for (int mt = 0; mt < 4; ++mt)
#pragma unroll
        for (int nt = 0; nt < 8; ++nt)
#pragma unroll
            for (int i = 0; i < 4; ++i) acc[mt][nt][i] = 0.0f;

    // prologue: prefetch chunks 0, 1
#pragma unroll
    for (int c = 0; c < NSTG - 1; ++c) {
        load_chunk(tid, AL + c * STG_BYTES, c, A, W, m_base, n_base);
        CP_COMMIT();
    }

    for (int k = 0; k < KC; ++k) {
        cp_wait<NSTG - 2>();           // chunk k resident
        __syncthreads();

        int pc = k + NSTG - 1;
        if (pc < KC)
            load_chunk(tid, AL + (pc % NSTG) * STG_BYTES, pc, A, W, m_base, n_base);
        CP_COMMIT();

        uint32_t sA = AL + (k % NSTG) * STG_BYTES;
        uint32_t sB = sA + A_BYTES;
#pragma unroll
        for (int ks = 0; ks < 4; ++ks) {           // 4 k8 steps per 32-chunk
            const int g = ks * 2 + ghi;
            uint32_t af[4][4], bf[4][4];
#pragma unroll
            for (int t = 0; t < 4; ++t)
                ldmatrix_x4(af[t], sA + aOff[t] + ((g ^ aSw[t]) << 4));
#pragma unroll
            for (int t = 0; t < 4; ++t)
                ldmatrix_x4(bf[t], sB + bOff[t] + ((g ^ bSw[t]) << 4));
            // round-to-nearest tf32 (unbiased; raw truncation biases the dot by ~1e-2)
#pragma unroll
            for (int t = 0; t < 4; ++t)
#pragma unroll
                for (int i = 0; i < 4; ++i) {
                    af[t][i] = f2tf32(af[t][i]);
                    bf[t][i] = f2tf32(bf[t][i]);
                }
#pragma unroll
            for (int mt = 0; mt < 4; ++mt)
#pragma unroll
                for (int nt = 0; nt < 8; ++nt) {
                    int i = nt >> 1, odd = nt & 1;
                    mma_tf32(acc[mt][nt], af[mt], bf[i][odd], bf[i][2 + odd]);
                }
        }
        __syncthreads();   // before next iter's producer reuses a drained stage
    }

    // ---------------- epilogue: bias + direct float2 stores ----------------
    float2 bv[8];
    const float2* b2 = reinterpret_cast<const float2*>(bias);
#pragma unroll
    for (int nt = 0; nt < 8; ++nt)
        bv[nt] = b2[(n_base + warp_n * 64 + nt * 8) / 2 + (lane & 3)];

#pragma unroll
    for (int mt = 0; mt < 4; ++mt) {
        int r0 = m_base + warp_m * 64 + mt * 16 + (lane >> 2);
#pragma unroll
        for (int nt = 0; nt < 8; ++nt) {
            int col = n_base + warp_n * 64 + nt * 8 + (lane & 3) * 2;
            float2 v0 = make_float2(acc[mt][nt][0] + bv[nt].x, acc[mt][nt][1] + bv[nt].y);
            float2 v1 = make_float2(acc[mt][nt][2] + bv[nt].x, acc[mt][nt][3] + bv[nt].y);
            *reinterpret_cast<float2*>(out + (size_t)r0 * N_TOTAL + col) = v0;
            *reinterpret_cast<float2*>(out + (size_t)(r0 + 8) * N_TOTAL + col) = v1;
        }
    }
}

// ---------------- Scan: mem_t = beta*mem + cur_t, in place over out_seq ----------------
__global__ void __launch_bounds__(256)
scan_kernel(float* __restrict__ out, const float* __restrict__ mem0,
            const float* __restrict__ beta) {
    int c = blockIdx.x * 256 + threadIdx.x;      // chain id: n*1024 + o
    float bt = __ldg(beta + (c & 1023));
    float m = __ldg(mem0 + c);
    float* p = out + c;
#pragma unroll 8
    for (int l = 0; l < 1024; ++l) {
        float v = p[(size_t)l << 16];
        m = fmaf(bt, m, v);
        p[(size_t)l << 16] = m;
    }
    out[(size_t)67108864 + c] = m;               // final_mem
}

// ---------------- launch ----------------
extern "C" void kernel_launch(void* const* d_in, const int* in_sizes, int n_in,
                              void* d_out, int out_size) {
    const float* spk  = (const float*)d_in[0];
    const float* mem0 = (const float*)d_in[1];
    const float* W    = (const float*)d_in[2];
    const float* bias = (const float*)d_in[3];
    const float* beta = (const float*)d_in[4];
    float* out = (float*)d_out;

    cudaFuncSetAttribute(gemm_tf32_kernel,
                         cudaFuncAttributeMaxDynamicSharedMemorySize, SMEM_DYN);

    dim3 grid(N_TOTAL / BN, M_TOTAL / BM);       // (4, 512), x fastest for W/L2 reuse
    gemm_tf32_kernel<<<grid, 256, SMEM_DYN>>>(spk, W, bias, out);
    scan_kernel<<<65536 / 256, 256>>>(out, mem0, beta);
}

// round 8
// speedup vs baseline: 1.6057x; 1.6057x over previous
#include <cuda_runtime.h>
#include <cuda_fp16.h>
#include <cstdint>
#include <cstddef>

// ---------------- Problem constants ----------------
// spk: [65536, 1024] fp32 (A, K-major), W: [1024, 1024] fp32 (rows = out dim, K-major),
// b: [1024], beta: [1024].
// out: out_seq [65536 x 1024] then final_mem [65536] at float offset 67108864.
#define M_TOTAL 65536
#define N_TOTAL 1024
#define K_TOTAL 1024

#define BM 128
#define BN 256
#define BK 64                      // 64 halves = 128 B per smem row
#define KC (K_TOTAL / BK)          // 16 chunks
#define NSTG 3
#define A_BYTES (BM * 128)         // 16 KB
#define B_BYTES (BN * 128)         // 32 KB
#define STG_BYTES (A_BYTES + B_BYTES)   // 48 KB
#define SMEM_DYN (1024 + NSTG * STG_BYTES)

// ---------------- fp16 scratch (static device arrays: no allocation) ----------------
__device__ __align__(16) __half g_spk_h[(size_t)M_TOTAL * K_TOTAL];   // 128 MB
__device__ __align__(16) __half g_W_h[(size_t)N_TOTAL * K_TOTAL];    // 2 MB

// ---------------- PTX helpers (baseline sm_80-class features only) ----------------
__device__ __forceinline__ uint32_t smem_u32(const void* p) {
    uint32_t r;
    asm("{ .reg .u64 t; cvta.to.shared.u64 t, %1; cvt.u32.u64 %0, t; }" : "=r"(r) : "l"(p));
    return r;
}
__device__ __forceinline__ void cp16(uint32_t dst, const void* src) {
    asm volatile("cp.async.cg.shared.global [%0], [%1], 16;"
                 :: "r"(dst), "l"(__cvta_generic_to_global(src)) : "memory");
}
#define CP_COMMIT() asm volatile("cp.async.commit_group;" ::: "memory")
template <int N>
__device__ __forceinline__ void cp_wait() {
    asm volatile("cp.async.wait_group %0;" :: "n"(N) : "memory");
}
__device__ __forceinline__ void ldmatrix_x4(uint32_t* r, uint32_t addr) {
    asm volatile("ldmatrix.sync.aligned.m8n8.x4.shared.b16 {%0,%1,%2,%3}, [%4];"
                 : "=r"(r[0]), "=r"(r[1]), "=r"(r[2]), "=r"(r[3]) : "r"(addr));
}
// pack two fp32 -> f16x2 register (lo = x, hi = y); PTX: d.lo = 2nd src, d.hi = 1st src
__device__ __forceinline__ uint32_t pack_h2(float x, float y) {
    uint32_t o;
    asm("cvt.rn.f16x2.f32 %0, %1, %2;" : "=r"(o) : "f"(y), "f"(x));
    return o;
}
__device__ __forceinline__ void mma_f16(float* d, const uint32_t* a,
                                        uint32_t b0, uint32_t b1) {
    asm volatile(
        "mma.sync.aligned.m16n8k16.row.col.f32.f16.f16.f32 "
        "{%0,%1,%2,%3}, {%4,%5,%6,%7}, {%8,%9}, {%0,%1,%2,%3};"
        : "+f"(d[0]), "+f"(d[1]), "+f"(d[2]), "+f"(d[3])
        : "r"(a[0]), "r"(a[1]), "r"(a[2]), "r"(a[3]), "r"(b0), "r"(b1));
}

// ---------------- fp32 -> fp16 conversion pre-passes ----------------
__global__ void __launch_bounds__(256)
cvt_spk_kernel(const float4* __restrict__ in) {
    uint4* outv = reinterpret_cast<uint4*>(g_spk_h);
    size_t i = (size_t)blockIdx.x * 256 + threadIdx.x;   // one uint4 (8 halves) per thread
    float4 a = in[2 * i], b = in[2 * i + 1];
    uint4 o;
    o.x = pack_h2(a.x, a.y);
    o.y = pack_h2(a.z, a.w);
    o.z = pack_h2(b.x, b.y);
    o.w = pack_h2(b.z, b.w);
    outv[i] = o;
}
__global__ void __launch_bounds__(256)
cvt_w_kernel(const float4* __restrict__ in) {
    uint4* outv = reinterpret_cast<uint4*>(g_W_h);
    size_t i = (size_t)blockIdx.x * 256 + threadIdx.x;
    float4 a = in[2 * i], b = in[2 * i + 1];
    uint4 o;
    o.x = pack_h2(a.x, a.y);
    o.y = pack_h2(a.z, a.w);
    o.z = pack_h2(b.x, b.y);
    o.w = pack_h2(b.z, b.w);
    outv[i] = o;
}

// ---------------- producer: gmem(fp16) -> swizzled smem ----------------
// A tile: 128 rows x 64 halves; B tile: 256 rows x 64 halves. Row = 128B.
// SW128: 16B-granule g stored at g ^ (row & 7).
__device__ __forceinline__ void load_chunk(int tid, uint32_t stage_base, int kc,
                                           const __half* __restrict__ A,
                                           const __half* __restrict__ W,
                                           int m_base, int n_base) {
    const __half* gA = A + (size_t)m_base * K_TOTAL + kc * BK;
    const __half* gB = W + (size_t)n_base * K_TOTAL + kc * BK;
    uint32_t sA = stage_base;
    uint32_t sB = stage_base + A_BYTES;
#pragma unroll
    for (int i = 0; i < 4; ++i) {                    // A: 1024 granules / 256 thr
        int idx = tid + i * 256;
        int row = idx >> 3, g = idx & 7;
        uint32_t sw = row * 128 + ((g ^ (row & 7)) << 4);
        cp16(sA + sw, gA + (size_t)row * K_TOTAL + g * 8);
    }
#pragma unroll
    for (int i = 0; i < 8; ++i) {                    // B: 2048 granules / 256 thr
        int idx = tid + i * 256;
        int row = idx >> 3, g = idx & 7;
        uint32_t sw = row * 128 + ((g ^ (row & 7)) << 4);
        cp16(sB + sw, gB + (size_t)row * K_TOTAL + g * 8);
    }
}

// ---------------- GEMM: cur = spk @ W^T + b -> out_seq region ----------------
__global__ void __launch_bounds__(256, 1)
gemm_f16_kernel(const float* __restrict__ bias, float* __restrict__ out) {
    extern __shared__ char smem[];
    const __half* A = g_spk_h;
    const __half* W = g_W_h;
    const int tid = threadIdx.x;
    const int lane = tid & 31;
    const int wid = tid >> 5;
    const int warp_m = wid & 1;        // 2 warp-rows  (64 M each)
    const int warp_n = wid >> 1;       // 4 warp-cols  (64 N each)
    const int n_base = blockIdx.x * BN;
    const int m_base = blockIdx.y * BM;

    uint32_t AL = (smem_u32(smem) + 1023) & ~1023u;

    // ldmatrix lane->row mapping (identical structure to working tf32 version):
    // lanes 0-7 -> rows 0-7 @ granule g, 8-15 -> rows 8-15 @ g,
    // 16-23 -> rows 0-7 @ g+1, 24-31 -> rows 8-15 @ g+1.
    const int lrow = ((lane >> 3) & 1) * 8 + (lane & 7);
    const int ghi = lane >> 4;
    uint32_t aOff[4], aSw[4], bOff[4], bSw[4];
#pragma unroll
    for (int t = 0; t < 4; ++t) {
        int ra = warp_m * 64 + t * 16 + lrow;
        int rb = warp_n * 64 + t * 16 + lrow;
        aOff[t] = ra * 128; aSw[t] = ra & 7;
        bOff[t] = rb * 128; bSw[t] = rb & 7;
    }

    float acc[4][8][4];
#pragma unroll
    for (int mt = 0; mt < 4; ++mt)
#pragma unroll
        for (int nt = 0; nt < 8; ++nt)
#pragma unroll
            for (int i = 0; i < 4; ++i) acc[mt][nt][i] = 0.0f;

    // prologue: prefetch chunks 0, 1
#pragma unroll
    for (int c = 0; c < NSTG - 1; ++c) {
        load_chunk(tid, AL + c * STG_BYTES, c, A, W, m_base, n_base);
        CP_COMMIT();
    }

    for (int k = 0; k < KC; ++k) {
        cp_wait<NSTG - 2>();           // chunk k resident
        __syncthreads();

        int pc = k + NSTG - 1;
        if (pc < KC)
            load_chunk(tid, AL + (pc % NSTG) * STG_BYTES, pc, A, W, m_base, n_base);
        CP_COMMIT();

        uint32_t sA = AL + (k % NSTG) * STG_BYTES;
        uint32_t sB = sA + A_BYTES;
#pragma unroll
        for (int ks = 0; ks < 4; ++ks) {           // 4 k16 steps per 64-half chunk
            const int g = ks * 2 + ghi;            // 2 granules (8 halves each) per k16
            uint32_t af[4][4], bf[4][4];
#pragma unroll
            for (int t = 0; t < 4; ++t)
                ldmatrix_x4(af[t], sA + aOff[t] + ((g ^ aSw[t]) << 4));
#pragma unroll
            for (int t = 0; t < 4; ++t)
                ldmatrix_x4(bf[t], sB + bOff[t] + ((g ^ bSw[t]) << 4));
#pragma unroll
            for (int mt = 0; mt < 4; ++mt)
#pragma unroll
                for (int nt = 0; nt < 8; ++nt) {
                    int i = nt >> 1, odd = nt & 1;
                    mma_f16(acc[mt][nt], af[mt], bf[i][odd], bf[i][2 + odd]);
                }
        }
        __syncthreads();   // before next iter's producer reuses a drained stage
    }

    // ---------------- epilogue: bias + direct float2 stores ----------------
    float2 bv[8];
    const float2* b2 = reinterpret_cast<const float2*>(bias);
#pragma unroll
    for (int nt = 0; nt < 8; ++nt)
        bv[nt] = b2[(n_base + warp_n * 64 + nt * 8) / 2 + (lane & 3)];

#pragma unroll
    for (int mt = 0; mt < 4; ++mt) {
        int r0 = m_base + warp_m * 64 + mt * 16 + (lane >> 2);
#pragma unroll
        for (int nt = 0; nt < 8; ++nt) {
            int col = n_base + warp_n * 64 + nt * 8 + (lane & 3) * 2;
            float2 v0 = make_float2(acc[mt][nt][0] + bv[nt].x, acc[mt][nt][1] + bv[nt].y);
            float2 v1 = make_float2(acc[mt][nt][2] + bv[nt].x, acc[mt][nt][3] + bv[nt].y);
            *reinterpret_cast<float2*>(out + (size_t)r0 * N_TOTAL + col) = v0;
            *reinterpret_cast<float2*>(out + (size_t)(r0 + 8) * N_TOTAL + col) = v1;
        }
    }
}

// ---------------- Scan: mem_t = beta*mem + cur_t, in place over out_seq ----------------
__global__ void __launch_bounds__(128)
scan_kernel(float* __restrict__ out, const float* __restrict__ mem0,
            const float* __restrict__ beta) {
    int c = blockIdx.x * 128 + threadIdx.x;      // chain id: n*1024 + o
    float bt = __ldg(beta + (c & 1023));
    float m = __ldg(mem0 + c);
    float* p = out + c;
#pragma unroll 8
    for (int l = 0; l < 1024; ++l) {
        float v = p[(size_t)l << 16];
        m = fmaf(bt, m, v);
        p[(size_t)l << 16] = m;
    }
    out[(size_t)67108864 + c] = m;               // final_mem
}

// ---------------- launch ----------------
extern "C" void kernel_launch(void* const* d_in, const int* in_sizes, int n_in,
                              void* d_out, int out_size) {
    const float* spk  = (const float*)d_in[0];
    const float* mem0 = (const float*)d_in[1];
    const float* W    = (const float*)d_in[2];
    const float* bias = (const float*)d_in[3];
    const float* beta = (const float*)d_in[4];
    float* out = (float*)d_out;

    cudaFuncSetAttribute(gemm_f16_kernel,
                         cudaFuncAttributeMaxDynamicSharedMemorySize, SMEM_DYN);

    // fp32 -> fp16 scratch (spk: 64M elems / 8 per thread; W: 1M / 8)
    cvt_spk_kernel<<<(M_TOTAL * (K_TOTAL / 8)) / 256, 256>>>((const float4*)spk);
    cvt_w_kernel<<<(N_TOTAL * (K_TOTAL / 8)) / 256, 256>>>((const float4*)W);

    dim3 grid(N_TOTAL / BN, M_TOTAL / BM);       // (4, 512), x fastest for W/L2 reuse
    gemm_f16_kernel<<<grid, 256, SMEM_DYN>>>(bias, out);
    scan_kernel<<<65536 / 128, 128>>>(out, mem0, beta);
}

// round 12
// speedup vs baseline: 1.8079x; 1.1259x over previous
#include <cuda_runtime.h>
#include <cuda_fp16.h>
#include <cstdint>
#include <cstddef>

// ---------------- Problem constants ----------------
// spk: [65536, 1024] fp32 (A, K-major), W: [1024, 1024] fp32 (rows = out dim, K-major),
// b: [1024], beta: [1024].
// out: out_seq [65536 x 1024] then final_mem [65536] at float offset 67108864.
#define M_TOTAL 65536
#define N_TOTAL 1024
#define K_TOTAL 1024

#define BM 128
#define BN 128
#define BK 64                      // 64 halves = 128 B per smem row
#define KC (K_TOTAL / BK)          // 16 chunks
#define NSTG 3
#define A_BYTES (BM * 128)         // 16 KB
#define B_BYTES (BN * 128)         // 16 KB
#define STG_BYTES (A_BYTES + B_BYTES)   // 32 KB
#define SMEM_DYN (1024 + NSTG * STG_BYTES)   // ~97 KB -> 2 CTAs/SM

// ---------------- fp16 scratch (static device arrays: no allocation) ----------------
__device__ __align__(16) __half g_spk_h[(size_t)M_TOTAL * K_TOTAL];   // 128 MB
__device__ __align__(16) __half g_W_h[(size_t)N_TOTAL * K_TOTAL];    // 2 MB

// ---------------- PTX helpers (baseline sm_80-class features only) ----------------
__device__ __forceinline__ uint32_t smem_u32(const void* p) {
    uint32_t r;
    asm("{ .reg .u64 t; cvta.to.shared.u64 t, %1; cvt.u32.u64 %0, t; }" : "=r"(r) : "l"(p));
    return r;
}
__device__ __forceinline__ void cp16(uint32_t dst, const void* src) {
    asm volatile("cp.async.cg.shared.global [%0], [%1], 16;"
                 :: "r"(dst), "l"(__cvta_generic_to_global(src)) : "memory");
}
#define CP_COMMIT() asm volatile("cp.async.commit_group;" ::: "memory")
template <int N>
__device__ __forceinline__ void cp_wait() {
    asm volatile("cp.async.wait_group %0;" :: "n"(N) : "memory");
}
__device__ __forceinline__ void ldmatrix_x4(uint32_t* r, uint32_t addr) {
    asm volatile("ldmatrix.sync.aligned.m8n8.x4.shared.b16 {%0,%1,%2,%3}, [%4];"
                 : "=r"(r[0]), "=r"(r[1]), "=r"(r[2]), "=r"(r[3]) : "r"(addr));
}
// pack two fp32 -> f16x2 register (lo = x, hi = y); PTX: d.lo = 2nd src, d.hi = 1st src
__device__ __forceinline__ uint32_t pack_h2(float x, float y) {
    uint32_t o;
    asm("cvt.rn.f16x2.f32 %0, %1, %2;" : "=r"(o) : "f"(y), "f"(x));
    return o;
}
__device__ __forceinline__ void mma_f16(float* d, const uint32_t* a,
                                        uint32_t b0, uint32_t b1) {
    asm volatile(
        "mma.sync.aligned.m16n8k16.row.col.f32.f16.f16.f32 "
        "{%0,%1,%2,%3}, {%4,%5,%6,%7}, {%8,%9}, {%0,%1,%2,%3};"
        : "+f"(d[0]), "+f"(d[1]), "+f"(d[2]), "+f"(d[3])
        : "r"(a[0]), "r"(a[1]), "r"(a[2]), "r"(a[3]), "r"(b0), "r"(b1));
}

// ---------------- fp32 -> fp16 conversion pre-passes ----------------
__global__ void __launch_bounds__(256)
cvt_spk_kernel(const float4* __restrict__ in) {
    uint4* outv = reinterpret_cast<uint4*>(g_spk_h);
    size_t i = (size_t)blockIdx.x * 256 + threadIdx.x;   // one uint4 (8 halves) per thread
    float4 a = in[2 * i], b = in[2 * i + 1];
    uint4 o;
    o.x = pack_h2(a.x, a.y);
    o.y = pack_h2(a.z, a.w);
    o.z = pack_h2(b.x, b.y);
    o.w = pack_h2(b.z, b.w);
    outv[i] = o;
}
__global__ void __launch_bounds__(256)
cvt_w_kernel(const float4* __restrict__ in) {
    uint4* outv = reinterpret_cast<uint4*>(g_W_h);
    size_t i = (size_t)blockIdx.x * 256 + threadIdx.x;
    float4 a = in[2 * i], b = in[2 * i + 1];
    uint4 o;
    o.x = pack_h2(a.x, a.y);
    o.y = pack_h2(a.z, a.w);
    o.z = pack_h2(b.x, b.y);
    o.w = pack_h2(b.z, b.w);
    outv[i] = o;
}

// ---------------- producer: gmem(fp16) -> swizzled smem ----------------
// A tile: 128 rows x 64 halves; B tile: 128 rows x 64 halves. Row = 128B.
// SW128: 16B-granule g stored at g ^ (row & 7).
__device__ __forceinline__ void load_chunk(int tid, uint32_t stage_base, int kc,
                                           const __half* __restrict__ A,
                                           const __half* __restrict__ W,
                                           int m_base, int n_base) {
    const __half* gA = A + (size_t)m_base * K_TOTAL + kc * BK;
    const __half* gB = W + (size_t)n_base * K_TOTAL + kc * BK;
    uint32_t sA = stage_base;
    uint32_t sB = stage_base + A_BYTES;
#pragma unroll
    for (int i = 0; i < 4; ++i) {                    // A: 1024 granules / 256 thr
        int idx = tid + i * 256;
        int row = idx >> 3, g = idx & 7;
        uint32_t sw = row * 128 + ((g ^ (row & 7)) << 4);
        cp16(sA + sw, gA + (size_t)row * K_TOTAL + g * 8);
    }
#pragma unroll
    for (int i = 0; i < 4; ++i) {                    // B: 1024 granules / 256 thr
        int idx = tid + i * 256;
        int row = idx >> 3, g = idx & 7;
        uint32_t sw = row * 128 + ((g ^ (row & 7)) << 4);
        cp16(sB + sw, gB + (size_t)row * K_TOTAL + g * 8);
    }
}

// ---------------- GEMM: cur = spk @ W^T + b -> out_seq region ----------------
__global__ void __launch_bounds__(256, 2)
gemm_f16_kernel(const float* __restrict__ bias, float* __restrict__ out) {
    extern __shared__ char smem[];
    const __half* A = g_spk_h;
    const __half* W = g_W_h;
    const int tid = threadIdx.x;
    const int lane = tid & 31;
    const int wid = tid >> 5;
    const int warp_m = wid & 1;        // 2 warp-rows  (64 M each)
    const int warp_n = wid >> 1;       // 4 warp-cols  (32 N each)
    const int n_base = blockIdx.x * BN;
    const int m_base = blockIdx.y * BM;

    uint32_t AL = (smem_u32(smem) + 1023) & ~1023u;

    // ldmatrix lane->row mapping:
    // lanes 0-7 -> rows 0-7 @ granule g, 8-15 -> rows 8-15 @ g,
    // 16-23 -> rows 0-7 @ g+1, 24-31 -> rows 8-15 @ g+1.
    const int lrow = ((lane >> 3) & 1) * 8 + (lane & 7);
    const int ghi = lane >> 4;
    uint32_t aOff[4], aSw[4], bOff[2], bSw[2];
#pragma unroll
    for (int t = 0; t < 4; ++t) {
        int ra = warp_m * 64 + t * 16 + lrow;
        aOff[t] = ra * 128; aSw[t] = ra & 7;
    }
#pragma unroll
    for (int t = 0; t < 2; ++t) {
        int rb = warp_n * 32 + t * 16 + lrow;
        bOff[t] = rb * 128; bSw[t] = rb & 7;
    }

    float acc[4][4][4];
#pragma unroll
    for (int mt = 0; mt < 4; ++mt)
#pragma unroll
        for (int nt = 0; nt < 4; ++nt)
#pragma unroll
            for (int i = 0; i < 4; ++i) acc[mt][nt][i] = 0.0f;

    // prologue: prefetch chunks 0, 1
#pragma unroll
    for (int c = 0; c < NSTG - 1; ++c) {
        load_chunk(tid, AL + c * STG_BYTES, c, A, W, m_base, n_base);
        CP_COMMIT();
    }

    for (int k = 0; k < KC; ++k) {
        cp_wait<NSTG - 2>();           // chunk k resident
        __syncthreads();

        int pc = k + NSTG - 1;
        if (pc < KC)
            load_chunk(tid, AL + (pc % NSTG) * STG_BYTES, pc, A, W, m_base, n_base);
        CP_COMMIT();

        uint32_t sA = AL + (k % NSTG) * STG_BYTES;
        uint32_t sB = sA + A_BYTES;
#pragma unroll
        for (int ks = 0; ks < 4; ++ks) {           // 4 k16 steps per 64-half chunk
            const int g = ks * 2 + ghi;            // 2 granules (8 halves each) per k16
            uint32_t af[4][4], bf[2][4];
#pragma unroll
            for (int t = 0; t < 4; ++t)
                ldmatrix_x4(af[t], sA + aOff[t] + ((g ^ aSw[t]) << 4));
#pragma unroll
            for (int t = 0; t < 2; ++t)
                ldmatrix_x4(bf[t], sB + bOff[t] + ((g ^ bSw[t]) << 4));
#pragma unroll
            for (int mt = 0; mt < 4; ++mt)
#pragma unroll
                for (int nt = 0; nt < 4; ++nt) {
                    int i = nt >> 1, odd = nt & 1;
                    mma_f16(acc[mt][nt], af[mt], bf[i][odd], bf[i][2 + odd]);
                }
        }
        __syncthreads();   // before next iter's producer reuses a drained stage
    }

    // ---------------- epilogue: bias + direct float2 stores ----------------
    float2 bv[4];
    const float2* b2 = reinterpret_cast<const float2*>(bias);
#pragma unroll
    for (int nt = 0; nt < 4; ++nt)
        bv[nt] = b2[(n_base + warp_n * 32 + nt * 8) / 2 + (lane & 3)];

#pragma unroll
    for (int mt = 0; mt < 4; ++mt) {
        int r0 = m_base + warp_m * 64 + mt * 16 + (lane >> 2);
#pragma unroll
        for (int nt = 0; nt < 4; ++nt) {
            int col = n_base + warp_n * 32 + nt * 8 + (lane & 3) * 2;
            float2 v0 = make_float2(acc[mt][nt][0] + bv[nt].x, acc[mt][nt][1] + bv[nt].y);
            float2 v1 = make_float2(acc[mt][nt][2] + bv[nt].x, acc[mt][nt][3] + bv[nt].y);
            *reinterpret_cast<float2*>(out + (size_t)r0 * N_TOTAL + col) = v0;
            *reinterpret_cast<float2*>(out + (size_t)(r0 + 8) * N_TOTAL + col) = v1;
        }
    }
}

// ---------------- Scan: mem_t = beta*mem + cur_t, in place over out_seq ----------------
// Double-buffered 16-wide batches: 16 independent loads in flight per thread while
// the previous 16 elements run the dependent fma chain + stores.
__global__ void __launch_bounds__(128)
scan_kernel(float* __restrict__ out, const float* __restrict__ mem0,
            const float* __restrict__ beta) {
    int c = blockIdx.x * 128 + threadIdx.x;      // chain id: n*1024 + o
    float bt = __ldg(beta + (c & 1023));
    float m = __ldg(mem0 + c);
    float* p = out + c;

    float v[16], w[16];
#pragma unroll
    for (int j = 0; j < 16; ++j) v[j] = p[(size_t)j << 16];

    for (int blk = 0; blk < 1024; blk += 16) {
        if (blk + 16 < 1024) {
#pragma unroll
            for (int j = 0; j < 16; ++j) w[j] = p[(size_t)(blk + 16 + j) << 16];
        }
#pragma unroll
        for (int j = 0; j < 16; ++j) {
            m = fmaf(bt, m, v[j]);
            p[(size_t)(blk + j) << 16] = m;
        }
#pragma unroll
        for (int j = 0; j < 16; ++j) v[j] = w[j];
    }
    out[(size_t)67108864 + c] = m;               // final_mem
}

// ---------------- launch ----------------
extern "C" void kernel_launch(void* const* d_in, const int* in_sizes, int n_in,
                              void* d_out, int out_size) {
    const float* spk  = (const float*)d_in[0];
    const float* mem0 = (const float*)d_in[1];
    const float* W    = (const float*)d_in[2];
    const float* bias = (const float*)d_in[3];
    const float* beta = (const float*)d_in[4];
    float* out = (float*)d_out;

    cudaFuncSetAttribute(gemm_f16_kernel,
                         cudaFuncAttributeMaxDynamicSharedMemorySize, SMEM_DYN);

    // fp32 -> fp16 scratch (spk: 64M elems / 8 per thread; W: 1M / 8)
    cvt_spk_kernel<<<(M_TOTAL * (K_TOTAL / 8)) / 256, 256>>>((const float4*)spk);
    cvt_w_kernel<<<(N_TOTAL * (K_TOTAL / 8)) / 256, 256>>>((const float4*)W);

    dim3 grid(N_TOTAL / BN, M_TOTAL / BM);       // (8, 512), x fastest for W/L2 reuse
    gemm_f16_kernel<<<grid, 256, SMEM_DYN>>>(bias, out);
    scan_kernel<<<65536 / 128, 128>>>(out, mem0, beta);
}

// round 13
// speedup vs baseline: 1.8603x; 1.0289x over previous
#include <cuda_runtime.h>
#include <cuda_fp16.h>
#include <cstdint>
#include <cstddef>

// ---------------- Problem constants ----------------
// spk: [65536, 1024] fp32 (A, K-major), W: [1024, 1024] fp32 (rows = out dim, K-major),
// b: [1024], beta: [1024].
// out: out_seq [65536 x 1024] then final_mem [65536] at float offset 67108864.
#define M_TOTAL 65536
#define N_TOTAL 1024
#define K_TOTAL 1024

#define BM 128
#define BN 128
#define BK 64                      // 64 halves = 128 B per smem row
#define KC (K_TOTAL / BK)          // 16 chunks
#define NSTG 3
#define A_BYTES (BM * 128)         // 16 KB
#define B_BYTES (BN * 128)         // 16 KB
#define STG_BYTES (A_BYTES + B_BYTES)   // 32 KB
#define SMEM_DYN (1024 + NSTG * STG_BYTES)   // ~97 KB; 2 CTAs/SM

// ---------------- fp16 scratch (static device arrays: no allocation) ----------------
__device__ __align__(16) __half g_spk_h[(size_t)M_TOTAL * K_TOTAL];   // 128 MB
__device__ __align__(16) __half g_W_h[(size_t)N_TOTAL * K_TOTAL];    // 2 MB

// ---------------- PTX helpers (baseline sm_80-class features only) ----------------
__device__ __forceinline__ uint32_t smem_u32(const void* p) {
    uint32_t r;
    asm("{ .reg .u64 t; cvta.to.shared.u64 t, %1; cvt.u32.u64 %0, t; }" : "=r"(r) : "l"(p));
    return r;
}
__device__ __forceinline__ void cp16(uint32_t dst, const void* src) {
    asm volatile("cp.async.cg.shared.global [%0], [%1], 16;"
                 :: "r"(dst), "l"(__cvta_generic_to_global(src)) : "memory");
}
#define CP_COMMIT() asm volatile("cp.async.commit_group;" ::: "memory")
template <int N>
__device__ __forceinline__ void cp_wait() {
    asm volatile("cp.async.wait_group %0;" :: "n"(N) : "memory");
}
__device__ __forceinline__ void ldmatrix_x4(uint32_t* r, uint32_t addr) {
    asm volatile("ldmatrix.sync.aligned.m8n8.x4.shared.b16 {%0,%1,%2,%3}, [%4];"
                 : "=r"(r[0]), "=r"(r[1]), "=r"(r[2]), "=r"(r[3]) : "r"(addr));
}
// pack two fp32 -> f16x2 register (lo = x, hi = y); PTX: d.lo = 2nd src, d.hi = 1st src
__device__ __forceinline__ uint32_t pack_h2(float x, float y) {
    uint32_t o;
    asm("cvt.rn.f16x2.f32 %0, %1, %2;" : "=r"(o) : "f"(y), "f"(x));
    return o;
}
__device__ __forceinline__ void mma_f16(float* d, const uint32_t* a,
                                        uint32_t b0, uint32_t b1) {
    asm volatile(
        "mma.sync.aligned.m16n8k16.row.col.f32.f16.f16.f32 "
        "{%0,%1,%2,%3}, {%4,%5,%6,%7}, {%8,%9}, {%0,%1,%2,%3};"
        : "+f"(d[0]), "+f"(d[1]), "+f"(d[2]), "+f"(d[3])
        : "r"(a[0]), "r"(a[1]), "r"(a[2]), "r"(a[3]), "r"(b0), "r"(b1));
}

// ---------------- fp32 -> fp16 conversion pre-passes ----------------
__global__ void __launch_bounds__(256)
cvt_spk_kernel(const float4* __restrict__ in) {
    uint4* outv = reinterpret_cast<uint4*>(g_spk_h);
    size_t i = (size_t)blockIdx.x * 256 + threadIdx.x;   // one uint4 (8 halves) per thread
    float4 a = in[2 * i], b = in[2 * i + 1];
    uint4 o;
    o.x = pack_h2(a.x, a.y);
    o.y = pack_h2(a.z, a.w);
    o.z = pack_h2(b.x, b.y);
    o.w = pack_h2(b.z, b.w);
    outv[i] = o;
}
__global__ void __launch_bounds__(256)
cvt_w_kernel(const float4* __restrict__ in) {
    uint4* outv = reinterpret_cast<uint4*>(g_W_h);
    size_t i = (size_t)blockIdx.x * 256 + threadIdx.x;
    float4 a = in[2 * i], b = in[2 * i + 1];
    uint4 o;
    o.x = pack_h2(a.x, a.y);
    o.y = pack_h2(a.z, a.w);
    o.z = pack_h2(b.x, b.y);
    o.w = pack_h2(b.z, b.w);
    outv[i] = o;
}

// ---------------- producer: gmem(fp16) -> swizzled smem (128 threads) ----------------
// A tile: 128 rows x 64 halves; B tile: 128 rows x 64 halves. Row = 128B.
// SW128: 16B-granule g stored at g ^ (row & 7).
__device__ __forceinline__ void load_chunk(int tid, uint32_t stage_base, int kc,
                                           const __half* __restrict__ A,
                                           const __half* __restrict__ W,
                                           int m_base, int n_base) {
    const __half* gA = A + (size_t)m_base * K_TOTAL + kc * BK;
    const __half* gB = W + (size_t)n_base * K_TOTAL + kc * BK;
    uint32_t sA = stage_base;
    uint32_t sB = stage_base + A_BYTES;
#pragma unroll
    for (int i = 0; i < 8; ++i) {                    // A: 1024 granules / 128 thr
        int idx = tid + i * 128;
        int row = idx >> 3, g = idx & 7;
        uint32_t sw = row * 128 + ((g ^ (row & 7)) << 4);
        cp16(sA + sw, gA + (size_t)row * K_TOTAL + g * 8);
    }
#pragma unroll
    for (int i = 0; i < 8; ++i) {                    // B: 1024 granules / 128 thr
        int idx = tid + i * 128;
        int row = idx >> 3, g = idx & 7;
        uint32_t sw = row * 128 + ((g ^ (row & 7)) << 4);
        cp16(sB + sw, gB + (size_t)row * K_TOTAL + g * 8);
    }
}

// ---------------- GEMM: cur = spk @ W^T + b -> out_seq region ----------------
// 128 threads = 4 warps in 2x2; each warp owns a 64x64 tile (32.8 FLOP/smem-byte).
__global__ void __launch_bounds__(128, 2)
gemm_f16_kernel(const float* __restrict__ bias, float* __restrict__ out) {
    extern __shared__ char smem[];
    const __half* A = g_spk_h;
    const __half* W = g_W_h;
    const int tid = threadIdx.x;
    const int lane = tid & 31;
    const int wid = tid >> 5;
    const int warp_m = wid & 1;        // 2 warp-rows (64 M each)
    const int warp_n = wid >> 1;       // 2 warp-cols (64 N each)
    const int n_base = blockIdx.x * BN;
    const int m_base = blockIdx.y * BM;

    uint32_t AL = (smem_u32(smem) + 1023) & ~1023u;

    // ldmatrix lane->row mapping:
    // lanes 0-7 -> rows 0-7 @ granule g, 8-15 -> rows 8-15 @ g,
    // 16-23 -> rows 0-7 @ g+1, 24-31 -> rows 8-15 @ g+1.
    const int lrow = ((lane >> 3) & 1) * 8 + (lane & 7);
    const int ghi = lane >> 4;
    uint32_t aOff[4], aSw[4], bOff[4], bSw[4];
#pragma unroll
    for (int t = 0; t < 4; ++t) {
        int ra = warp_m * 64 + t * 16 + lrow;
        int rb = warp_n * 64 + t * 16 + lrow;
        aOff[t] = ra * 128; aSw[t] = ra & 7;
        bOff[t] = rb * 128; bSw[t] = rb & 7;
    }

    float acc[4][8][4];
#pragma unroll
    for (int mt = 0; mt < 4; ++mt)
#pragma unroll
        for (int nt = 0; nt < 8; ++nt)
#pragma unroll
            for (int i = 0; i < 4; ++i) acc[mt][nt][i] = 0.0f;

    // prologue: prefetch chunks 0, 1
#pragma unroll
    for (int c = 0; c < NSTG - 1; ++c) {
        load_chunk(tid, AL + c * STG_BYTES, c, A, W, m_base, n_base);
        CP_COMMIT();
    }

    uint32_t af[2][4][4], bf[2][4][4];   // double-buffered fragments across ks-steps

    for (int k = 0; k < KC; ++k) {
        cp_wait<NSTG - 2>();           // chunk k resident
        __syncthreads();

        int pc = k + NSTG - 1;
        if (pc < KC)
            load_chunk(tid, AL + (pc % NSTG) * STG_BYTES, pc, A, W, m_base, n_base);
        CP_COMMIT();

        uint32_t sA = AL + (k % NSTG) * STG_BYTES;
        uint32_t sB = sA + A_BYTES;

        // preload fragments for ks=0
        {
            const int g = ghi;
#pragma unroll
            for (int t = 0; t < 4; ++t)
                ldmatrix_x4(af[0][t], sA + aOff[t] + ((g ^ aSw[t]) << 4));
#pragma unroll
            for (int t = 0; t < 4; ++t)
                ldmatrix_x4(bf[0][t], sB + bOff[t] + ((g ^ bSw[t]) << 4));
        }

#pragma unroll
        for (int ks = 0; ks < 4; ++ks) {           // 4 k16 steps per 64-half chunk
            const int cur = ks & 1, nxt = cur ^ 1;
            if (ks < 3) {                          // prefetch ks+1 under this ks's HMMAs
                const int g = (ks + 1) * 2 + ghi;
#pragma unroll
                for (int t = 0; t < 4; ++t)
                    ldmatrix_x4(af[nxt][t], sA + aOff[t] + ((g ^ aSw[t]) << 4));
#pragma unroll
                for (int t = 0; t < 4; ++t)
                    ldmatrix_x4(bf[nxt][t], sB + bOff[t] + ((g ^ bSw[t]) << 4));
            }
#pragma unroll
            for (int mt = 0; mt < 4; ++mt)
#pragma unroll
                for (int nt = 0; nt < 8; ++nt) {
                    int i = nt >> 1, odd = nt & 1;
                    mma_f16(acc[mt][nt], af[cur][mt], bf[cur][i][odd], bf[cur][i][2 + odd]);
                }
        }
        __syncthreads();   // before next iter's producer reuses a drained stage
    }

    // ---------------- epilogue: bias + direct float2 stores ----------------
    float2 bv[8];
    const float2* b2 = reinterpret_cast<const float2*>(bias);
#pragma unroll
    for (int nt = 0; nt < 8; ++nt)
        bv[nt] = b2[(n_base + warp_n * 64 + nt * 8) / 2 + (lane & 3)];

#pragma unroll
    for (int mt = 0; mt < 4; ++mt) {
        int r0 = m_base + warp_m * 64 + mt * 16 + (lane >> 2);
#pragma unroll
        for (int nt = 0; nt < 8; ++nt) {
            int col = n_base + warp_n * 64 + nt * 8 + (lane & 3) * 2;
            float2 v0 = make_float2(acc[mt][nt][0] + bv[nt].x, acc[mt][nt][1] + bv[nt].y);
            float2 v1 = make_float2(acc[mt][nt][2] + bv[nt].x, acc[mt][nt][3] + bv[nt].y);
            *reinterpret_cast<float2*>(out + (size_t)r0 * N_TOTAL + col) = v0;
            *reinterpret_cast<float2*>(out + (size_t)(r0 + 8) * N_TOTAL + col) = v1;
        }
    }
}

// ---------------- Scan: mem_t = beta*mem + cur_t, in place over out_seq ----------------
// Double-buffered 32-wide batches with streaming hints (data touched exactly once).
__global__ void __launch_bounds__(128)
scan_kernel(float* __restrict__ out, const float* __restrict__ mem0,
            const float* __restrict__ beta) {
    int c = blockIdx.x * 128 + threadIdx.x;      // chain id: n*1024 + o
    float bt = __ldg(beta + (c & 1023));
    float m = __ldg(mem0 + c);
    float* p = out + c;

    float v[32], w[32];
#pragma unroll
    for (int j = 0; j < 32; ++j) v[j] = __ldcs(p + ((size_t)j << 16));

    for (int blk = 0; blk < 1024; blk += 32) {
        if (blk + 32 < 1024) {
#pragma unroll
            for (int j = 0; j < 32; ++j) w[j] = __ldcs(p + ((size_t)(blk + 32 + j) << 16));
        }
#pragma unroll
        for (int j = 0; j < 32; ++j) {
            m = fmaf(bt, m, v[j]);
            __stcs(p + ((size_t)(blk + j) << 16), m);
        }
#pragma unroll
        for (int j = 0; j < 32; ++j) v[j] = w[j];
    }
    out[(size_t)67108864 + c] = m;               // final_mem
}

// ---------------- launch ----------------
extern "C" void kernel_launch(void* const* d_in, const int* in_sizes, int n_in,
                              void* d_out, int out_size) {
    const float* spk  = (const float*)d_in[0];
    const float* mem0 = (const float*)d_in[1];
    const float* W    = (const float*)d_in[2];
    const float* bias = (const float*)d_in[3];
    const float* beta = (const float*)d_in[4];
    float* out = (float*)d_out;

    cudaFuncSetAttribute(gemm_f16_kernel,
                         cudaFuncAttributeMaxDynamicSharedMemorySize, SMEM_DYN);

    // fp32 -> fp16 scratch (spk: 64M elems / 8 per thread; W: 1M / 8)
    cvt_spk_kernel<<<(M_TOTAL * (K_TOTAL / 8)) / 256, 256>>>((const float4*)spk);
    cvt_w_kernel<<<(N_TOTAL * (K_TOTAL / 8)) / 256, 256>>>((const float4*)W);

    dim3 grid(N_TOTAL / BN, M_TOTAL / BM);       // (8, 512), x fastest for W/L2 reuse
    gemm_f16_kernel<<<grid, 128, SMEM_DYN>>>(bias, out);
    scan_kernel<<<65536 / 128, 128>>>(out, mem0, beta);
}